// round 14
// baseline (speedup 1.0000x reference)
#include <cuda_runtime.h>
#include <cuda_fp16.h>
#include <cstdint>

// ---------------- problem dims ----------------
#define N_OUT   11008
#define K_IN    4096
#define T_TOK   32
#define GROUP   128

// ---------------- tiling ----------------
#define KSPLIT  8
#define GPC     4                       // groups per CTA: 8*4*128 = 4096 = K_IN
#define NTILE   128
#define NBLK    (N_OUT / NTILE)         // 86
#define THREADS 256                     // 8 warps, each owns n-slice of 16

// ---------------- smem layout ----------------
// A buffers: 2 x (32 rows x 128 fp16, 272B pitch)   [tokens x k]
// B buffers: 2 x (128 rows x 128 fp16, 272B pitch)  [k x n]
// ZS: GPC x 128 int (staged zeros)   SS: GPC x 128 float (staged scales)
#define A_SZ1   (32 * 272)              // 8704
#define BOFF    (2 * A_SZ1)             // 17408
#define B_SZ1   (128 * 272)             // 34816
#define ZOFF    (BOFF + 2 * B_SZ1)      // 87040
#define SOFF    (ZOFF + GPC * 128 * 4)  // 89088
#define SMEM_DYN (SOFF + GPC * 128 * 4) // 91136 -> 2 CTAs/SM

__device__ float g_part[KSPLIT * T_TOK * N_OUT];
__device__ int   g_cnt[NBLK];           // zero-init; reset by fixup each launch

// ---------------- PTX helpers ----------------
__device__ __forceinline__ uint32_t smem_u32(const void* p) {
    uint32_t a;
    asm("{ .reg .u64 t; cvta.to.shared.u64 t, %1; cvt.u32.u64 %0, t; }"
        : "=r"(a) : "l"(p));
    return a;
}
#define LDSMX4(r, addr) \
    asm volatile("ldmatrix.sync.aligned.m8n8.x4.shared.b16 {%0,%1,%2,%3}, [%4];" \
        : "=r"((r)[0]), "=r"((r)[1]), "=r"((r)[2]), "=r"((r)[3]) : "r"(addr))
#define LDSMX4T(r, addr) \
    asm volatile("ldmatrix.sync.aligned.m8n8.x4.trans.shared.b16 {%0,%1,%2,%3}, [%4];" \
        : "=r"((r)[0]), "=r"((r)[1]), "=r"((r)[2]), "=r"((r)[3]) : "r"(addr))

#define MMA16816(d, a, b0, b1) \
    asm volatile("mma.sync.aligned.m16n8k16.row.col.f32.f16.f16.f32 " \
        "{%0,%1,%2,%3}, {%4,%5,%6,%7}, {%8,%9}, {%0,%1,%2,%3};" \
        : "+f"((d)[0]), "+f"((d)[1]), "+f"((d)[2]), "+f"((d)[3]) \
        : "r"((a)[0]), "r"((a)[1]), "r"((a)[2]), "r"((a)[3]), "r"(b0), "r"(b1))

// ---------------- main kernel (GEMM + fused split-K fixup) ----------------
__global__ __launch_bounds__(THREADS, 2)
void awq_mma(const float* __restrict__ x,
             const int*   __restrict__ qw,
             const int*   __restrict__ qz,
             const float* __restrict__ sc,
             const float* __restrict__ bias,
             float*       __restrict__ out)
{
    extern __shared__ __align__(16) char smem[];
    const uint32_t sb = smem_u32(smem);

    const int tid  = threadIdx.x;
    const int lane = tid & 31;
    const int w    = tid >> 5;          // warp 0..7, n-slice w*16
    const int n0   = blockIdx.x * NTILE;
    const int ks   = blockIdx.y;

    int*   zs = reinterpret_cast<int*>(smem + ZOFF);
    float* ss = reinterpret_cast<float*>(smem + SOFF);

    // q load geometry: krow = tid>>5 (0..7), int4 col = lane
    const int krow = tid >> 5;
    const int4* qcol = reinterpret_cast<const int4*>(
        qw + (size_t)(ks * GPC * GROUP + krow) * N_OUT + n0) + lane;
    const size_t qrow8 = (size_t)8 * (N_OUT / 4);   // int4 stride: 8 k-rows
    const size_t qgrp  = (size_t)GROUP * (N_OUT / 4);

    // ---- prologue: stage q for group 0 in registers ----
    int4 qr[16];
#pragma unroll
    for (int it = 0; it < 16; it++)
        qr[it] = __ldcs(qcol + (size_t)it * qrow8);

    // ---- prologue: stage z/s for ALL groups into smem (overlaps q LDGs) ----
#pragma unroll
    for (int i = tid; i < GPC * 128; i += THREADS) {
        const int gi = i >> 7, j = i & 127;
        zs[i] = qz[(size_t)(ks * GPC + gi) * N_OUT + n0 + j];
        ss[i] = sc[(size_t)(ks * GPC + gi) * N_OUT + n0 + j];
    }
    __syncthreads();   // zs/ss visible before group-0 convert

    // ldmatrix lane bases (buffer 0)
    const uint32_t a_lane = sb + (uint32_t)(lane & 15) * 272u
                               + (uint32_t)(lane >> 4) * 16u;
    const uint32_t b_lane = sb + BOFF
        + (uint32_t)(((lane >> 3) & 1) * 8 + (lane & 7)) * 272u
        + (uint32_t)(w * 16 + (lane >> 4) * 8) * 2u;

    const __half2 mhalf = __floats2half2_rn(-1040.0f, -1040.0f);

    float master[2][2][4];
#pragma unroll
    for (int mt = 0; mt < 2; mt++)
#pragma unroll
        for (int nt = 0; nt < 2; nt++)
#pragma unroll
            for (int r = 0; r < 4; r++) master[mt][nt][r] = 0.0f;

    for (int gi = 0; gi < GPC; gi++) {
        const int g   = ks * GPC + gi;
        const int buf = gi & 1;

        // ---- convert qr -> B[buf] fp16 [k][n] via integer magic ----
        // t = q + (0x6410 - z) => halfbits(1024 + (q-z+16)); w = t - 1040
        {
            const int4 z4 = *reinterpret_cast<const int4*>(&zs[gi * 128 + lane * 4]);
            const int c0 = 0x6410 - z4.x, c1 = 0x6410 - z4.y;
            const int c2 = 0x6410 - z4.z, c3 = 0x6410 - z4.w;
            char* bc = smem + BOFF + buf * B_SZ1 + krow * 272 + lane * 8;
#pragma unroll
            for (int it = 0; it < 16; it++) {
                const int4 q = qr[it];
                const uint32_t p01 = (uint32_t)(q.y + c1) * 65536u + (uint32_t)(q.x + c0);
                const uint32_t p23 = (uint32_t)(q.w + c3) * 65536u + (uint32_t)(q.z + c2);
                __half2 w01 = __hadd2(*reinterpret_cast<const __half2*>(&p01), mhalf);
                __half2 w23 = __hadd2(*reinterpret_cast<const __half2*>(&p23), mhalf);
                uint2 pk;
                pk.x = *reinterpret_cast<uint32_t*>(&w01);
                pk.y = *reinterpret_cast<uint32_t*>(&w23);
                *reinterpret_cast<uint2*>(bc + it * (8 * 272)) = pk;
            }
        }

        // ---- fill A[buf]: x fp32 (L2) -> fp16, rows = tokens ----
        {
            const int t = tid >> 3, seg = tid & 7;
            const float4* xp = reinterpret_cast<const float4*>(
                x + (size_t)t * K_IN + g * GROUP + seg * 16);
            char* ar = smem + buf * A_SZ1 + t * 272 + seg * 32;
#pragma unroll
            for (int q4 = 0; q4 < 4; q4++) {
                const float4 v = xp[q4];
                __half2 h0 = __floats2half2_rn(v.x, v.y);
                __half2 h1 = __floats2half2_rn(v.z, v.w);
                uint2 pk;
                pk.x = *reinterpret_cast<uint32_t*>(&h0);
                pk.y = *reinterpret_cast<uint32_t*>(&h1);
                *reinterpret_cast<uint2*>(ar + q4 * 8) = pk;
            }
        }

        // ---- stage next group's q (regs free after convert) ----
        if (gi + 1 < GPC) {
#pragma unroll
            for (int it = 0; it < 16; it++)
                qr[it] = __ldcs(qcol + (size_t)(gi + 1) * qgrp + (size_t)it * qrow8);
        }

        __syncthreads();       // A[buf], B[buf] visible; buf safe to read

        // ---- MMA: 8 k-steps ----
        float gacc[2][2][4];
#pragma unroll
        for (int mt = 0; mt < 2; mt++)
#pragma unroll
            for (int nt = 0; nt < 2; nt++)
#pragma unroll
                for (int r = 0; r < 4; r++) gacc[mt][nt][r] = 0.0f;

        const uint32_t ab = a_lane + buf * A_SZ1;
        const uint32_t bb = b_lane + buf * B_SZ1;
#pragma unroll
        for (int j = 0; j < 8; j++) {
            uint32_t a0[4], a1[4], b[4];
            LDSMX4(a0, ab + j * 32);
            LDSMX4(a1, ab + 16 * 272 + j * 32);
            LDSMX4T(b, bb + j * (16 * 272));
            MMA16816(gacc[0][0], a0, b[0], b[1]);
            MMA16816(gacc[0][1], a0, b[2], b[3]);
            MMA16816(gacc[1][0], a1, b[0], b[1]);
            MMA16816(gacc[1][1], a1, b[2], b[3]);
        }

        // ---- per-group scale into master acc (scales from smem) ----
#pragma unroll
        for (int nt = 0; nt < 2; nt++) {
            const float2 s2 = *reinterpret_cast<const float2*>(
                &ss[gi * 128 + w * 16 + nt * 8 + (lane & 3) * 2]);
#pragma unroll
            for (int mt = 0; mt < 2; mt++) {
                master[mt][nt][0] = fmaf(s2.x, gacc[mt][nt][0], master[mt][nt][0]);
                master[mt][nt][1] = fmaf(s2.y, gacc[mt][nt][1], master[mt][nt][1]);
                master[mt][nt][2] = fmaf(s2.x, gacc[mt][nt][2], master[mt][nt][2]);
                master[mt][nt][3] = fmaf(s2.y, gacc[mt][nt][3], master[mt][nt][3]);
            }
        }
    }

    // ---- write split-K partials ----
    const int mrow = lane >> 2;
#pragma unroll
    for (int mt = 0; mt < 2; mt++)
#pragma unroll
        for (int nt = 0; nt < 2; nt++) {
            const int nn = n0 + w * 16 + nt * 8 + (lane & 3) * 2;
            float* p = g_part + ((size_t)ks * T_TOK + mt * 16 + mrow) * N_OUT + nn;
            *reinterpret_cast<float2*>(p) =
                make_float2(master[mt][nt][0], master[mt][nt][1]);
            *reinterpret_cast<float2*>(p + (size_t)8 * N_OUT) =
                make_float2(master[mt][nt][2], master[mt][nt][3]);
        }

    // ---- fused split-K fixup: last CTA of this n-tile reduces + bias ----
    __threadfence();           // make this thread's partials visible gpu-wide
    __syncthreads();           // all threads' partials written + fenced
    int* flag = reinterpret_cast<int*>(smem);    // smem reuse (mainloop done)
    if (tid == 0) {
        const int old = atomicAdd(&g_cnt[blockIdx.x], 1);
        flag[0] = (old == KSPLIT - 1);
    }
    __syncthreads();
    if (flag[0]) {
        if (tid == 0) g_cnt[blockIdx.x] = 0;     // re-arm for next launch
        const float4* part4 = reinterpret_cast<const float4*>(g_part);
        const float4* bias4 = reinterpret_cast<const float4*>(bias);
        float4*       out4  = reinterpret_cast<float4*>(out);
#pragma unroll
        for (int i = 0; i < 4; i++) {
            const int idx = tid + THREADS * i;   // 0..1023
            const int t   = idx >> 5;            // token 0..31
            const int c4  = idx & 31;            // float4 col within tile
            const int nb4 = (n0 >> 2) + c4;
            float4 s = bias4[nb4];
#pragma unroll
            for (int sp = 0; sp < KSPLIT; sp++) {
                const float4 v =
                    part4[((size_t)(sp * T_TOK + t) * N_OUT >> 2) + nb4];
                s.x += v.x; s.y += v.y; s.z += v.z; s.w += v.w;
            }
            out4[((size_t)t * N_OUT >> 2) + nb4] = s;
        }
    }
}

extern "C" void kernel_launch(void* const* d_in, const int* in_sizes, int n_in,
                              void* d_out, int out_size)
{
    const float* x    = (const float*)d_in[0];
    const int*   qw   = (const int*)  d_in[1];
    const int*   qz   = (const int*)  d_in[2];
    const float* sc   = (const float*)d_in[3];
    const float* bias = (const float*)d_in[4];
    float*       out  = (float*)d_out;

    // Unconditional (idempotent, capture-legal): no cross-call state.
    cudaFuncSetAttribute(awq_mma, cudaFuncAttributeMaxDynamicSharedMemorySize,
                         SMEM_DYN);

    dim3 grid(NBLK, KSPLIT);
    awq_mma<<<grid, THREADS, SMEM_DYN>>>(x, qw, qz, sc, bias, out);
}